// round 11
// baseline (speedup 1.0000x reference)
#include <cuda_runtime.h>
#include <cuda_bf16.h>
#include <cstdint>

#define HW    448
#define NTOK  200704
#define NWIN  4096
#define NHEADS 6

// ---------------- scratch (device globals; no allocation allowed) ----------
__device__ __nv_bfloat16 g_xh[(size_t)NTOK * 192];
__device__ __nv_bfloat16 g_xl[(size_t)NTOK * 192];
__device__ float         g_qkv[(size_t)NTOK * 576];
__device__ __nv_bfloat16 g_ah[(size_t)NTOK * 192];
__device__ __nv_bfloat16 g_al[(size_t)NTOK * 192];
__device__ __nv_bfloat16 g_wqh[576 * 192], g_wql[576 * 192];
__device__ __nv_bfloat16 g_wph[192 * 192], g_wpl[192 * 192];

// ---------------- helpers ---------------------------------------------------
__device__ __forceinline__ uint32_t smem_u32(const void* p) {
    uint32_t a;
    asm("{ .reg .u64 t; cvta.to.shared.u64 t, %1; cvt.u32.u64 %0, t; }" : "=r"(a) : "l"(p));
    return a;
}
__device__ __forceinline__ void fma2(unsigned long long& d, unsigned long long a, unsigned long long b) {
    asm("fma.rn.f32x2 %0, %1, %2, %0;" : "+l"(d) : "l"(a), "l"(b));
}
__device__ __forceinline__ unsigned long long pk2(float v) {
    unsigned long long r; asm("mov.b64 %0, {%1, %1};" : "=l"(r) : "f"(v)); return r;
}
__device__ __forceinline__ float f2lo(unsigned long long v) { return __uint_as_float((unsigned)(v & 0xffffffffu)); }
__device__ __forceinline__ float f2hi(unsigned long long v) { return __uint_as_float((unsigned)(v >> 32)); }

__device__ __forceinline__ void ldsm4(uint32_t* r, uint32_t addr) {
    asm volatile("ldmatrix.sync.aligned.m8n8.x4.shared.b16 {%0,%1,%2,%3}, [%4];"
                 : "=r"(r[0]), "=r"(r[1]), "=r"(r[2]), "=r"(r[3]) : "r"(addr));
}
__device__ __forceinline__ void mma16816(float* c, const uint32_t* a, uint32_t b0, uint32_t b1) {
    asm volatile("mma.sync.aligned.m16n8k16.row.col.f32.bf16.bf16.f32 "
                 "{%0,%1,%2,%3}, {%4,%5,%6,%7}, {%8,%9}, {%0,%1,%2,%3};"
                 : "+f"(c[0]), "+f"(c[1]), "+f"(c[2]), "+f"(c[3])
                 : "r"(a[0]), "r"(a[1]), "r"(a[2]), "r"(a[3]), "r"(b0), "r"(b1));
}
__device__ __forceinline__ void cpa16(uint32_t dst, const void* src) {
    asm volatile("cp.async.cg.shared.global [%0], [%1], 16;" :: "r"(dst), "l"(src));
}

__device__ __forceinline__ int tok2pix(int t) {
    int w = t / 49, p = t - w * 49;
    int hr = (w >> 6) * 7 + p / 7;
    int wr = (w & 63) * 7 + (p % 7);
    int h = hr + 3; if (h >= HW) h -= HW;
    int ww = wr + 3; if (ww >= HW) ww -= HW;
    return h * HW + ww;
}

// ---------------------------------------------------------------------------
// Kernel 1: cyclic shift + window partition + transpose + bf16 hi/lo split
// ---------------------------------------------------------------------------
__global__ void gather_kernel(const float* __restrict__ x) {
    __shared__ float s[32][33];
    int pb = blockIdx.x * 32, cb = blockIdx.y * 32;
    int tx = threadIdx.x, ty = threadIdx.y;

    int pr = pb + tx;
    int hr = pr / HW, wr = pr - hr * HW;
    int hs = hr + 3; if (hs >= HW) hs -= HW;
    int ws = wr + 3; if (ws >= HW) ws -= HW;
    s[ty][tx] = x[(size_t)(cb + ty) * NTOK + hs * HW + ws];
    __syncthreads();

    int pr2 = pb + ty;
    int hr2 = pr2 / HW, wr2 = pr2 - hr2 * HW;
    int t = ((hr2 / 7) * 64 + (wr2 / 7)) * 49 + (hr2 % 7) * 7 + (wr2 % 7);
    float v = s[tx][ty];
    __nv_bfloat16 h = __float2bfloat16(v);
    size_t o = (size_t)t * 192 + cb + tx;
    g_xh[o] = h;
    g_xl[o] = __float2bfloat16(v - __bfloat162float(h));
}

__global__ void wsplit_kernel(const float* __restrict__ w,
                              __nv_bfloat16* __restrict__ h,
                              __nv_bfloat16* __restrict__ l, int n) {
    int i = blockIdx.x * 256 + threadIdx.x;
    if (i < n) {
        float v = w[i];
        __nv_bfloat16 a = __float2bfloat16(v);
        h[i] = a;
        l[i] = __float2bfloat16(v - __bfloat162float(a));
    }
}

// ---------------------------------------------------------------------------
// Kernel 2/4: HMMA bf16-split GEMM, cp.async triple-buffered over K chunks.
//   Tile M=128, N=96, BK=32, K=192 (6 chunks). 8 warps: 4m x 2n of 32x48.
// ---------------------------------------------------------------------------
#define PITCHB 80
#define ST_AH 0
#define ST_AL 10240
#define ST_BH 20480
#define ST_BL 28160
#define ST_SZ 35840
#define NSTAGE 3
#define SMEM_TOTAL (NSTAGE * ST_SZ)       // 107520

__device__ __forceinline__ void issue_chunk(
    uint32_t sb, int stage, int c, int tid, int m0, int n0,
    const __nv_bfloat16* Ahi, const __nv_bfloat16* Alo,
    const __nv_bfloat16* Bhi, const __nv_bfloat16* Blo) {
    int kb = c * 32;
    uint32_t st = sb + stage * ST_SZ;
    #pragma unroll
    for (int i = 0; i < 7; i++) {
        int gid = tid + i * 256;
        if (i < 4) {                       // A planes: gid 0..1023
            int plane = gid >> 9, r = (gid >> 2) & 127, s = gid & 3;
            const __nv_bfloat16* src = (plane ? Alo : Ahi) + (size_t)(m0 + r) * 192 + kb + s * 8;
            cpa16(st + (plane ? ST_AL : ST_AH) + r * PITCHB + s * 16, src);
        } else {                           // B planes: gid 1024..1791
            int g2 = gid - 1024;
            int plane = g2 >= 384, rr = (plane ? g2 - 384 : g2) >> 2, s = g2 & 3;
            const __nv_bfloat16* src = (plane ? Blo : Bhi) + (size_t)(n0 + rr) * 192 + kb + s * 8;
            cpa16(st + (plane ? ST_BL : ST_BH) + rr * PITCHB + s * 16, src);
        }
    }
    asm volatile("cp.async.commit_group;" ::: "memory");
}

__device__ __forceinline__ void compute_chunk(
    uint32_t sb, int stage, uint32_t aoff, uint32_t boff, float c[2][6][4]) {
    uint32_t st = sb + stage * ST_SZ;
    uint32_t pah = st + ST_AH + aoff, pal = st + ST_AL + aoff;
    uint32_t pbh = st + ST_BH + boff, pbl = st + ST_BL + boff;
    #pragma unroll
    for (int k = 0; k < 2; k++) {
        uint32_t ah0[4], ah1[4], al0[4], al1[4];
        uint32_t bh0[4], bh1[4], bh2[4], bl0[4], bl1[4], bl2[4];
        ldsm4(ah0, pah + k * 32);
        ldsm4(ah1, pah + k * 32 + 16 * PITCHB);
        ldsm4(bh0, pbh + k * 32);
        ldsm4(bh1, pbh + k * 32 + 16 * PITCHB);
        ldsm4(bh2, pbh + k * 32 + 32 * PITCHB);
        ldsm4(al0, pal + k * 32);
        ldsm4(al1, pal + k * 32 + 16 * PITCHB);
        ldsm4(bl0, pbl + k * 32);
        ldsm4(bl1, pbl + k * 32 + 16 * PITCHB);
        ldsm4(bl2, pbl + k * 32 + 32 * PITCHB);
        // pass 0: Ah * Bh
        mma16816(c[0][0], ah0, bh0[0], bh0[1]);
        mma16816(c[0][1], ah0, bh0[2], bh0[3]);
        mma16816(c[0][2], ah0, bh1[0], bh1[1]);
        mma16816(c[0][3], ah0, bh1[2], bh1[3]);
        mma16816(c[0][4], ah0, bh2[0], bh2[1]);
        mma16816(c[0][5], ah0, bh2[2], bh2[3]);
        mma16816(c[1][0], ah1, bh0[0], bh0[1]);
        mma16816(c[1][1], ah1, bh0[2], bh0[3]);
        mma16816(c[1][2], ah1, bh1[0], bh1[1]);
        mma16816(c[1][3], ah1, bh1[2], bh1[3]);
        mma16816(c[1][4], ah1, bh2[0], bh2[1]);
        mma16816(c[1][5], ah1, bh2[2], bh2[3]);
        // pass 1: Ah * Bl
        mma16816(c[0][0], ah0, bl0[0], bl0[1]);
        mma16816(c[0][1], ah0, bl0[2], bl0[3]);
        mma16816(c[0][2], ah0, bl1[0], bl1[1]);
        mma16816(c[0][3], ah0, bl1[2], bl1[3]);
        mma16816(c[0][4], ah0, bl2[0], bl2[1]);
        mma16816(c[0][5], ah0, bl2[2], bl2[3]);
        mma16816(c[1][0], ah1, bl0[0], bl0[1]);
        mma16816(c[1][1], ah1, bl0[2], bl0[3]);
        mma16816(c[1][2], ah1, bl1[0], bl1[1]);
        mma16816(c[1][3], ah1, bl1[2], bl1[3]);
        mma16816(c[1][4], ah1, bl2[0], bl2[1]);
        mma16816(c[1][5], ah1, bl2[2], bl2[3]);
        // pass 2: Al * Bh
        mma16816(c[0][0], al0, bh0[0], bh0[1]);
        mma16816(c[0][1], al0, bh0[2], bh0[3]);
        mma16816(c[0][2], al0, bh1[0], bh1[1]);
        mma16816(c[0][3], al0, bh1[2], bh1[3]);
        mma16816(c[0][4], al0, bh2[0], bh2[1]);
        mma16816(c[0][5], al0, bh2[2], bh2[3]);
        mma16816(c[1][0], al1, bh0[0], bh0[1]);
        mma16816(c[1][1], al1, bh0[2], bh0[3]);
        mma16816(c[1][2], al1, bh1[0], bh1[1]);
        mma16816(c[1][3], al1, bh1[2], bh1[3]);
        mma16816(c[1][4], al1, bh2[0], bh2[1]);
        mma16816(c[1][5], al1, bh2[2], bh2[3]);
    }
}

template<int MODE>
__global__ __launch_bounds__(256, 2) void hmma_gemm(
    const __nv_bfloat16* __restrict__ Ahi, const __nv_bfloat16* __restrict__ Alo,
    const __nv_bfloat16* __restrict__ Bhi, const __nv_bfloat16* __restrict__ Blo,
    const float* __restrict__ bias, float* __restrict__ C, int ncols) {
    extern __shared__ char smem[];
    uint32_t sb = smem_u32(smem);
    int tid = threadIdx.x;
    int n0 = blockIdx.x * 96, m0 = blockIdx.y * 128;
    int lane = tid & 31, warp = tid >> 5;
    int wm = (warp & 3) * 32, wn = (warp >> 2) * 48;

    uint32_t aoff = (uint32_t)(wm + (lane & 15)) * PITCHB + ((lane >> 4) << 4);
    uint32_t boff = (uint32_t)(wn + ((lane >> 4) << 3) + (lane & 7)) * PITCHB
                    + (((lane >> 3) & 1) << 4);

    float c[2][6][4];
    #pragma unroll
    for (int i = 0; i < 2; i++)
        #pragma unroll
        for (int j = 0; j < 6; j++)
            #pragma unroll
            for (int e = 0; e < 4; e++) c[i][j][e] = 0.f;

    issue_chunk(sb, 0, 0, tid, m0, n0, Ahi, Alo, Bhi, Blo);
    issue_chunk(sb, 1, 1, tid, m0, n0, Ahi, Alo, Bhi, Blo);
    issue_chunk(sb, 2, 2, tid, m0, n0, Ahi, Alo, Bhi, Blo);

    #pragma unroll 1
    for (int ch = 0; ch < 6; ch++) {
        if (ch <= 3)      asm volatile("cp.async.wait_group 2;" ::: "memory");
        else if (ch == 4) asm volatile("cp.async.wait_group 1;" ::: "memory");
        else              asm volatile("cp.async.wait_group 0;" ::: "memory");
        __syncthreads();
        int stg = ch % NSTAGE;
        compute_chunk(sb, stg, aoff, boff, c);
        if (ch + 3 < 6) {
            __syncthreads();
            issue_chunk(sb, stg, ch + 3, tid, m0, n0, Ahi, Alo, Bhi, Blo);
        }
    }

    int rbase = m0 + wm + (lane >> 2);
    int cbase = n0 + wn + (lane & 3) * 2;
    if (MODE == 0) {
        #pragma unroll
        for (int mt = 0; mt < 2; mt++) {
            #pragma unroll
            for (int half = 0; half < 2; half++) {
                int row = rbase + mt * 16 + half * 8;
                float* Cr = C + (size_t)row * ncols;
                #pragma unroll
                for (int nt = 0; nt < 6; nt++) {
                    int col = cbase + nt * 8;
                    float2 b2 = *(const float2*)(bias + col);
                    float2 o;
                    o.x = c[mt][nt][half * 2 + 0] + b2.x;
                    o.y = c[mt][nt][half * 2 + 1] + b2.y;
                    *(float2*)(Cr + col) = o;
                }
            }
        }
    } else {
        #pragma unroll
        for (int mt = 0; mt < 2; mt++) {
            #pragma unroll
            for (int half = 0; half < 2; half++) {
                int row = rbase + mt * 16 + half * 8;
                int pix = tok2pix(row);
                #pragma unroll
                for (int nt = 0; nt < 6; nt++) {
                    int col = cbase + nt * 8;
                    C[(size_t)col * NTOK + pix]       = c[mt][nt][half * 2 + 0] + bias[col];
                    C[(size_t)(col + 1) * NTOK + pix] = c[mt][nt][half * 2 + 1] + bias[col + 1];
                }
            }
        }
    }
}

// ---------------------------------------------------------------------------
// Kernel 3: per-(window, head) attention, register-tiled, f32x2 throughout.
//   PV phase fully vectorized: float4 S loads, LDS.128 V loads.
// ---------------------------------------------------------------------------
__global__ __launch_bounds__(128) void attn_kernel(const float* __restrict__ qkv,
                                                   const float* __restrict__ table,
                                                   __nv_bfloat16* __restrict__ oh,
                                                   __nv_bfloat16* __restrict__ ol) {
    int blk = blockIdx.x;
    int w = blk / NHEADS, head = blk - w * NHEADS;

    __shared__ __align__(16) float qs[52][36];
    __shared__ __align__(16) float ks[52][36];
    __shared__ __align__(16) float vs[52][36];
    __shared__ __align__(16) float S[52][56];
    __shared__ float tb[25];
    __shared__ int   reg[52];

    int tid = threadIdx.x;
    const float scale = 0.17677669529663687f;  // 1/sqrt(32)
    size_t base = (size_t)w * 49 * 576 + head * 32;

    for (int i = tid; i < 49 * 32; i += 128) {
        int n = i >> 5, d = i & 31;
        size_t o = base + (size_t)n * 576 + d;
        qs[n][d] = qkv[o] * scale;
        ks[n][d] = qkv[o + 192];
        vs[n][d] = qkv[o + 384];
    }
    // zero pad rows 49..51 of q/k/v (keeps padded tiles finite)
    if (tid < 3 * 32) {
        int n = 49 + (tid >> 5), d = tid & 31;
        qs[n][d] = 0.f; ks[n][d] = 0.f; vs[n][d] = 0.f;
    }
    if (tid < 52) {
        int t = tid < 49 ? tid : 48;
        int wy = w >> 6, wx = w & 63;
        int hr = wy * 7 + t / 7, wr = wx * 7 + t % 7;
        reg[tid] = ((hr >= 441) + (hr >= 445)) * 3 + (wr >= 441) + (wr >= 445);
    }
    if (tid < 25) {
        int d = tid - 12;
        int idx = d < 0 ? d + 169 : d;     // jnp negative-index wraparound
        tb[tid] = table[idx * NHEADS + head];
    }
    __syncthreads();

    // score phase: 13x13 tiles of 4x4, packed f32x2 dots
    for (int ti = tid; ti < 169; ti += 128) {
        int n0 = (ti / 13) * 4, m0 = (ti % 13) * 4;
        unsigned long long acc2[4][4];
        #pragma unroll
        for (int i = 0; i < 4; i++)
            #pragma unroll
            for (int j = 0; j < 4; j++) acc2[i][j] = 0ULL;
        #pragma unroll
        for (int dc = 0; dc < 8; dc++) {
            ulonglong2 q2[4], k2[4];
            #pragma unroll
            for (int i = 0; i < 4; i++) q2[i] = *(const ulonglong2*)&qs[n0 + i][dc * 4];
            #pragma unroll
            for (int j = 0; j < 4; j++) k2[j] = *(const ulonglong2*)&ks[m0 + j][dc * 4];
            #pragma unroll
            for (int i = 0; i < 4; i++)
                #pragma unroll
                for (int j = 0; j < 4; j++) {
                    fma2(acc2[i][j], q2[i].x, k2[j].x);
                    fma2(acc2[i][j], q2[i].y, k2[j].y);
                }
        }
        #pragma unroll
        for (int i = 0; i < 4; i++) {
            int n = n0 + i;
            int nr = n / 7, nc = n % 7;
            #pragma unroll
            for (int j = 0; j < 4; j++) {
                int m = m0 + j;
                float v = f2lo(acc2[i][j]) + f2hi(acc2[i][j])
                        + tb[(nr - m / 7) + (nc - m % 7) + 12];
                if (reg[n] != reg[m]) v -= 100.f;
                S[n][m] = v;
            }
        }
    }
    __syncthreads();

    int lane = tid & 31, wrp = tid >> 5;
    for (int n = wrp; n < 49; n += 4) {
        float v0 = S[n][lane];
        bool has2 = (lane + 32) < 49;
        float v1 = has2 ? S[n][lane + 32] : -1e30f;
        float mx = fmaxf(v0, v1);
        #pragma unroll
        for (int o = 16; o; o >>= 1) mx = fmaxf(mx, __shfl_xor_sync(0xffffffffu, mx, o));
        float e0 = __expf(v0 - mx);
        float e1 = has2 ? __expf(v1 - mx) : 0.f;
        float sm = e0 + e1;
        #pragma unroll
        for (int o = 16; o; o >>= 1) sm += __shfl_xor_sync(0xffffffffu, sm, o);
        float inv = 1.f / sm;
        S[n][lane] = e0 * inv;
        if (has2) S[n][lane + 32] = e1 * inv;
        if (lane < 3) S[n][49 + lane] = 0.f;   // zero pad for vectorized PV
    }
    __syncthreads();

    // PV phase: 13 n-tiles x 8 d-tiles of 4n x 4d (104 threads),
    // float4 S loads + LDS.128 V loads, f32x2 math.
    if (tid < 104) {
        int n0 = (tid >> 3) * 4, d0 = (tid & 7) * 4;
        unsigned long long a2[4][2];
        #pragma unroll
        for (int i = 0; i < 4; i++) { a2[i][0] = 0ULL; a2[i][1] = 0ULL; }
        #pragma unroll 1
        for (int mt = 0; mt < 13; mt++) {
            int m = mt * 4;
            float4 s4[4];
            #pragma unroll
            for (int i = 0; i < 4; i++) s4[i] = *(const float4*)&S[n0 + i][m];
            #pragma unroll
            for (int j = 0; j < 4; j++) {
                ulonglong2 v4 = *(const ulonglong2*)&vs[m + j][d0];
                #pragma unroll
                for (int i = 0; i < 4; i++) {
                    float sv = (j == 0) ? s4[i].x : (j == 1) ? s4[i].y
                             : (j == 2) ? s4[i].z : s4[i].w;
                    unsigned long long s2 = pk2(sv);
                    fma2(a2[i][0], s2, v4.x);
                    fma2(a2[i][1], s2, v4.y);
                }
            }
        }
        #pragma unroll
        for (int i = 0; i < 4; i++) {
            int n = n0 + i;
            if (n < 49) {
                float o0 = f2lo(a2[i][0]), o1 = f2hi(a2[i][0]);
                float o2 = f2lo(a2[i][1]), o3 = f2hi(a2[i][1]);
                __nv_bfloat16 h0 = __float2bfloat16(o0), h1 = __float2bfloat16(o1);
                __nv_bfloat16 h2 = __float2bfloat16(o2), h3 = __float2bfloat16(o3);
                __nv_bfloat162 hh0, hh1, ll0, ll1;
                hh0.x = h0; hh0.y = h1; hh1.x = h2; hh1.y = h3;
                ll0.x = __float2bfloat16(o0 - __bfloat162float(h0));
                ll0.y = __float2bfloat16(o1 - __bfloat162float(h1));
                ll1.x = __float2bfloat16(o2 - __bfloat162float(h2));
                ll1.y = __float2bfloat16(o3 - __bfloat162float(h3));
                size_t ob = ((size_t)w * 49 + n) * 192 + head * 32 + d0;
                *(__nv_bfloat162*)(oh + ob)     = hh0;
                *(__nv_bfloat162*)(oh + ob + 2) = hh1;
                *(__nv_bfloat162*)(ol + ob)     = ll0;
                *(__nv_bfloat162*)(ol + ob + 2) = ll1;
            }
        }
    }
}

// ---------------------------------------------------------------------------
extern "C" void kernel_launch(void* const* d_in, const int* in_sizes, int n_in,
                              void* d_out, int out_size) {
    (void)in_sizes; (void)n_in; (void)out_size;
    const float* x      = (const float*)d_in[0];
    const float* qkv_w  = (const float*)d_in[1];
    const float* qkv_b  = (const float*)d_in[2];
    const float* proj_w = (const float*)d_in[3];
    const float* proj_b = (const float*)d_in[4];
    const float* table  = (const float*)d_in[5];
    float* out = (float*)d_out;

    __nv_bfloat16 *xh, *xl, *ah, *al, *wqh, *wql, *wph, *wpl;
    float *qkvb;
    cudaGetSymbolAddress((void**)&xh,  g_xh);
    cudaGetSymbolAddress((void**)&xl,  g_xl);
    cudaGetSymbolAddress((void**)&qkvb, g_qkv);
    cudaGetSymbolAddress((void**)&ah,  g_ah);
    cudaGetSymbolAddress((void**)&al,  g_al);
    cudaGetSymbolAddress((void**)&wqh, g_wqh);
    cudaGetSymbolAddress((void**)&wql, g_wql);
    cudaGetSymbolAddress((void**)&wph, g_wph);
    cudaGetSymbolAddress((void**)&wpl, g_wpl);

    cudaFuncSetAttribute(hmma_gemm<0>, cudaFuncAttributeMaxDynamicSharedMemorySize, SMEM_TOTAL);
    cudaFuncSetAttribute(hmma_gemm<1>, cudaFuncAttributeMaxDynamicSharedMemorySize, SMEM_TOTAL);

    wsplit_kernel<<<(576 * 192 + 255) / 256, 256>>>(qkv_w, wqh, wql, 576 * 192);
    wsplit_kernel<<<(192 * 192 + 255) / 256, 256>>>(proj_w, wph, wpl, 192 * 192);
    gather_kernel<<<dim3(NTOK / 32, 192 / 32), dim3(32, 32)>>>(x);

    hmma_gemm<0><<<dim3(6, NTOK / 128), 256, SMEM_TOTAL>>>(xh, xl, wqh, wql, qkv_b, qkvb, 576);
    attn_kernel<<<NWIN * NHEADS, 128>>>(qkvb, table, ah, al);
    hmma_gemm<1><<<dim3(2, NTOK / 128), 256, SMEM_TOTAL>>>(ah, al, wph, wpl, proj_b, out, 192);
}

// round 13
// speedup vs baseline: 1.0762x; 1.0762x over previous
#include <cuda_runtime.h>
#include <cuda_bf16.h>
#include <cstdint>

#define HW    448
#define NTOK  200704
#define NWIN  4096
#define NHEADS 6

// ---------------- scratch (device globals; no allocation allowed) ----------
__device__ __nv_bfloat16 g_xh[(size_t)NTOK * 192];
__device__ __nv_bfloat16 g_xl[(size_t)NTOK * 192];
__device__ float         g_qkv[(size_t)NTOK * 576];
__device__ __nv_bfloat16 g_ah[(size_t)NTOK * 192];
__device__ __nv_bfloat16 g_al[(size_t)NTOK * 192];
__device__ __nv_bfloat16 g_wqh[576 * 192], g_wql[576 * 192];
__device__ __nv_bfloat16 g_wph[192 * 192], g_wpl[192 * 192];

// ---------------- helpers ---------------------------------------------------
__device__ __forceinline__ uint32_t smem_u32(const void* p) {
    uint32_t a;
    asm("{ .reg .u64 t; cvta.to.shared.u64 t, %1; cvt.u32.u64 %0, t; }" : "=r"(a) : "l"(p));
    return a;
}
__device__ __forceinline__ void fma2(unsigned long long& d, unsigned long long a, unsigned long long b) {
    asm("fma.rn.f32x2 %0, %1, %2, %0;" : "+l"(d) : "l"(a), "l"(b));
}
__device__ __forceinline__ unsigned long long pk2(float v) {
    unsigned long long r; asm("mov.b64 %0, {%1, %1};" : "=l"(r) : "f"(v)); return r;
}
__device__ __forceinline__ float f2lo(unsigned long long v) { return __uint_as_float((unsigned)(v & 0xffffffffu)); }
__device__ __forceinline__ float f2hi(unsigned long long v) { return __uint_as_float((unsigned)(v >> 32)); }

__device__ __forceinline__ void ldsm4(uint32_t* r, uint32_t addr) {
    asm volatile("ldmatrix.sync.aligned.m8n8.x4.shared.b16 {%0,%1,%2,%3}, [%4];"
                 : "=r"(r[0]), "=r"(r[1]), "=r"(r[2]), "=r"(r[3]) : "r"(addr));
}
__device__ __forceinline__ void mma16816(float* c, const uint32_t* a, uint32_t b0, uint32_t b1) {
    asm volatile("mma.sync.aligned.m16n8k16.row.col.f32.bf16.bf16.f32 "
                 "{%0,%1,%2,%3}, {%4,%5,%6,%7}, {%8,%9}, {%0,%1,%2,%3};"
                 : "+f"(c[0]), "+f"(c[1]), "+f"(c[2]), "+f"(c[3])
                 : "r"(a[0]), "r"(a[1]), "r"(a[2]), "r"(a[3]), "r"(b0), "r"(b1));
}
__device__ __forceinline__ void cpa16(uint32_t dst, const void* src) {
    asm volatile("cp.async.cg.shared.global [%0], [%1], 16;" :: "r"(dst), "l"(src));
}

__device__ __forceinline__ int tok2pix(int t) {
    int w = t / 49, p = t - w * 49;
    int hr = (w >> 6) * 7 + p / 7;
    int wr = (w & 63) * 7 + (p % 7);
    int h = hr + 3; if (h >= HW) h -= HW;
    int ww = wr + 3; if (ww >= HW) ww -= HW;
    return h * HW + ww;
}

// ---------------------------------------------------------------------------
// Kernel 1: cyclic shift + window partition + transpose + bf16 hi/lo split
// ---------------------------------------------------------------------------
__global__ void gather_kernel(const float* __restrict__ x) {
    __shared__ float s[32][33];
    int pb = blockIdx.x * 32, cb = blockIdx.y * 32;
    int tx = threadIdx.x, ty = threadIdx.y;

    int pr = pb + tx;
    int hr = pr / HW, wr = pr - hr * HW;
    int hs = hr + 3; if (hs >= HW) hs -= HW;
    int ws = wr + 3; if (ws >= HW) ws -= HW;
    s[ty][tx] = x[(size_t)(cb + ty) * NTOK + hs * HW + ws];
    __syncthreads();

    int pr2 = pb + ty;
    int hr2 = pr2 / HW, wr2 = pr2 - hr2 * HW;
    int t = ((hr2 / 7) * 64 + (wr2 / 7)) * 49 + (hr2 % 7) * 7 + (wr2 % 7);
    float v = s[tx][ty];
    __nv_bfloat16 h = __float2bfloat16(v);
    size_t o = (size_t)t * 192 + cb + tx;
    g_xh[o] = h;
    g_xl[o] = __float2bfloat16(v - __bfloat162float(h));
}

__global__ void wsplit_kernel(const float* __restrict__ w,
                              __nv_bfloat16* __restrict__ h,
                              __nv_bfloat16* __restrict__ l, int n) {
    int i = blockIdx.x * 256 + threadIdx.x;
    if (i < n) {
        float v = w[i];
        __nv_bfloat16 a = __float2bfloat16(v);
        h[i] = a;
        l[i] = __float2bfloat16(v - __bfloat162float(a));
    }
}

// ---------------------------------------------------------------------------
// Kernel 2/4: HMMA bf16-split GEMM, cp.async triple-buffered over K chunks.
//   Tile M=128, N=96, BK=32, K=192 (6 chunks). 8 warps: 4m x 2n of 32x48.
// ---------------------------------------------------------------------------
#define PITCHB 80
#define ST_AH 0
#define ST_AL 10240
#define ST_BH 20480
#define ST_BL 28160
#define ST_SZ 35840
#define NSTAGE 3
#define SMEM_TOTAL (NSTAGE * ST_SZ)       // 107520

__device__ __forceinline__ void issue_chunk(
    uint32_t sb, int stage, int c, int tid, int m0, int n0,
    const __nv_bfloat16* Ahi, const __nv_bfloat16* Alo,
    const __nv_bfloat16* Bhi, const __nv_bfloat16* Blo) {
    int kb = c * 32;
    uint32_t st = sb + stage * ST_SZ;
    #pragma unroll
    for (int i = 0; i < 7; i++) {
        int gid = tid + i * 256;
        if (i < 4) {                       // A planes: gid 0..1023
            int plane = gid >> 9, r = (gid >> 2) & 127, s = gid & 3;
            const __nv_bfloat16* src = (plane ? Alo : Ahi) + (size_t)(m0 + r) * 192 + kb + s * 8;
            cpa16(st + (plane ? ST_AL : ST_AH) + r * PITCHB + s * 16, src);
        } else {                           // B planes: gid 1024..1791
            int g2 = gid - 1024;
            int plane = g2 >= 384, rr = (plane ? g2 - 384 : g2) >> 2, s = g2 & 3;
            const __nv_bfloat16* src = (plane ? Blo : Bhi) + (size_t)(n0 + rr) * 192 + kb + s * 8;
            cpa16(st + (plane ? ST_BL : ST_BH) + rr * PITCHB + s * 16, src);
        }
    }
    asm volatile("cp.async.commit_group;" ::: "memory");
}

__device__ __forceinline__ void compute_chunk(
    uint32_t sb, int stage, uint32_t aoff, uint32_t boff, float c[2][6][4]) {
    uint32_t st = sb + stage * ST_SZ;
    uint32_t pah = st + ST_AH + aoff, pal = st + ST_AL + aoff;
    uint32_t pbh = st + ST_BH + boff, pbl = st + ST_BL + boff;
    #pragma unroll
    for (int k = 0; k < 2; k++) {
        uint32_t ah0[4], ah1[4], al0[4], al1[4];
        uint32_t bh0[4], bh1[4], bh2[4], bl0[4], bl1[4], bl2[4];
        ldsm4(ah0, pah + k * 32);
        ldsm4(ah1, pah + k * 32 + 16 * PITCHB);
        ldsm4(bh0, pbh + k * 32);
        ldsm4(bh1, pbh + k * 32 + 16 * PITCHB);
        ldsm4(bh2, pbh + k * 32 + 32 * PITCHB);
        ldsm4(al0, pal + k * 32);
        ldsm4(al1, pal + k * 32 + 16 * PITCHB);
        ldsm4(bl0, pbl + k * 32);
        ldsm4(bl1, pbl + k * 32 + 16 * PITCHB);
        ldsm4(bl2, pbl + k * 32 + 32 * PITCHB);
        // pass 0: Ah * Bh
        mma16816(c[0][0], ah0, bh0[0], bh0[1]);
        mma16816(c[0][1], ah0, bh0[2], bh0[3]);
        mma16816(c[0][2], ah0, bh1[0], bh1[1]);
        mma16816(c[0][3], ah0, bh1[2], bh1[3]);
        mma16816(c[0][4], ah0, bh2[0], bh2[1]);
        mma16816(c[0][5], ah0, bh2[2], bh2[3]);
        mma16816(c[1][0], ah1, bh0[0], bh0[1]);
        mma16816(c[1][1], ah1, bh0[2], bh0[3]);
        mma16816(c[1][2], ah1, bh1[0], bh1[1]);
        mma16816(c[1][3], ah1, bh1[2], bh1[3]);
        mma16816(c[1][4], ah1, bh2[0], bh2[1]);
        mma16816(c[1][5], ah1, bh2[2], bh2[3]);
        // pass 1: Ah * Bl
        mma16816(c[0][0], ah0, bl0[0], bl0[1]);
        mma16816(c[0][1], ah0, bl0[2], bl0[3]);
        mma16816(c[0][2], ah0, bl1[0], bl1[1]);
        mma16816(c[0][3], ah0, bl1[2], bl1[3]);
        mma16816(c[0][4], ah0, bl2[0], bl2[1]);
        mma16816(c[0][5], ah0, bl2[2], bl2[3]);
        mma16816(c[1][0], ah1, bl0[0], bl0[1]);
        mma16816(c[1][1], ah1, bl0[2], bl0[3]);
        mma16816(c[1][2], ah1, bl1[0], bl1[1]);
        mma16816(c[1][3], ah1, bl1[2], bl1[3]);
        mma16816(c[1][4], ah1, bl2[0], bl2[1]);
        mma16816(c[1][5], ah1, bl2[2], bl2[3]);
        // pass 2: Al * Bh
        mma16816(c[0][0], al0, bh0[0], bh0[1]);
        mma16816(c[0][1], al0, bh0[2], bh0[3]);
        mma16816(c[0][2], al0, bh1[0], bh1[1]);
        mma16816(c[0][3], al0, bh1[2], bh1[3]);
        mma16816(c[0][4], al0, bh2[0], bh2[1]);
        mma16816(c[0][5], al0, bh2[2], bh2[3]);
        mma16816(c[1][0], al1, bh0[0], bh0[1]);
        mma16816(c[1][1], al1, bh0[2], bh0[3]);
        mma16816(c[1][2], al1, bh1[0], bh1[1]);
        mma16816(c[1][3], al1, bh1[2], bh1[3]);
        mma16816(c[1][4], al1, bh2[0], bh2[1]);
        mma16816(c[1][5], al1, bh2[2], bh2[3]);
    }
}

template<int MODE>
__global__ __launch_bounds__(256, 2) void hmma_gemm(
    const __nv_bfloat16* __restrict__ Ahi, const __nv_bfloat16* __restrict__ Alo,
    const __nv_bfloat16* __restrict__ Bhi, const __nv_bfloat16* __restrict__ Blo,
    const float* __restrict__ bias, float* __restrict__ C, int ncols) {
    extern __shared__ char smem[];
    uint32_t sb = smem_u32(smem);
    int tid = threadIdx.x;
    int n0 = blockIdx.x * 96, m0 = blockIdx.y * 128;
    int lane = tid & 31, warp = tid >> 5;
    int wm = (warp & 3) * 32, wn = (warp >> 2) * 48;

    uint32_t aoff = (uint32_t)(wm + (lane & 15)) * PITCHB + ((lane >> 4) << 4);
    uint32_t boff = (uint32_t)(wn + ((lane >> 4) << 3) + (lane & 7)) * PITCHB
                    + (((lane >> 3) & 1) << 4);

    float c[2][6][4];
    #pragma unroll
    for (int i = 0; i < 2; i++)
        #pragma unroll
        for (int j = 0; j < 6; j++)
            #pragma unroll
            for (int e = 0; e < 4; e++) c[i][j][e] = 0.f;

    issue_chunk(sb, 0, 0, tid, m0, n0, Ahi, Alo, Bhi, Blo);
    issue_chunk(sb, 1, 1, tid, m0, n0, Ahi, Alo, Bhi, Blo);
    issue_chunk(sb, 2, 2, tid, m0, n0, Ahi, Alo, Bhi, Blo);

    #pragma unroll 1
    for (int ch = 0; ch < 6; ch++) {
        if (ch <= 3)      asm volatile("cp.async.wait_group 2;" ::: "memory");
        else if (ch == 4) asm volatile("cp.async.wait_group 1;" ::: "memory");
        else              asm volatile("cp.async.wait_group 0;" ::: "memory");
        __syncthreads();
        int stg = ch % NSTAGE;
        compute_chunk(sb, stg, aoff, boff, c);
        if (ch + 3 < 6) {
            __syncthreads();
            issue_chunk(sb, stg, ch + 3, tid, m0, n0, Ahi, Alo, Bhi, Blo);
        }
    }

    int rbase = m0 + wm + (lane >> 2);
    int cbase = n0 + wn + (lane & 3) * 2;
    if (MODE == 0) {
        #pragma unroll
        for (int mt = 0; mt < 2; mt++) {
            #pragma unroll
            for (int half = 0; half < 2; half++) {
                int row = rbase + mt * 16 + half * 8;
                float* Cr = C + (size_t)row * ncols;
                #pragma unroll
                for (int nt = 0; nt < 6; nt++) {
                    int col = cbase + nt * 8;
                    float2 b2 = *(const float2*)(bias + col);
                    float2 o;
                    o.x = c[mt][nt][half * 2 + 0] + b2.x;
                    o.y = c[mt][nt][half * 2 + 1] + b2.y;
                    *(float2*)(Cr + col) = o;
                }
            }
        }
    } else {
        #pragma unroll
        for (int mt = 0; mt < 2; mt++) {
            #pragma unroll
            for (int half = 0; half < 2; half++) {
                int row = rbase + mt * 16 + half * 8;
                int pix = tok2pix(row);
                #pragma unroll
                for (int nt = 0; nt < 6; nt++) {
                    int col = cbase + nt * 8;
                    C[(size_t)col * NTOK + pix]       = c[mt][nt][half * 2 + 0] + bias[col];
                    C[(size_t)(col + 1) * NTOK + pix] = c[mt][nt][half * 2 + 1] + bias[col + 1];
                }
            }
        }
    }
}

// ---------------------------------------------------------------------------
// Kernel 3: per-(window, head) attention, 192 threads, float4 gmem loads,
//   f32x2 score phase (1 tile/thread), scalar PV (R9-proven).
// ---------------------------------------------------------------------------
__global__ __launch_bounds__(192) void attn_kernel(const float* __restrict__ qkv,
                                                   const float* __restrict__ table,
                                                   __nv_bfloat16* __restrict__ oh,
                                                   __nv_bfloat16* __restrict__ ol) {
    int blk = blockIdx.x;
    int w = blk / NHEADS, head = blk - w * NHEADS;

    __shared__ __align__(16) float qs[52][36];
    __shared__ __align__(16) float ks[52][36];
    __shared__ __align__(16) float vs[49][36];
    __shared__ float S[52][56];
    __shared__ float tb[25];
    __shared__ int   reg[52];

    int tid = threadIdx.x;
    const float scale = 0.17677669529663687f;  // 1/sqrt(32)
    size_t base = (size_t)w * 49 * 576 + head * 32;

    // vectorized load: 49 tokens x 8 float4 per matrix
    for (int i = tid; i < 49 * 8; i += 192) {
        int n = i >> 3, d4 = (i & 7) << 2;
        const float* row = qkv + base + (size_t)n * 576 + d4;
        float4 q4 = *(const float4*)(row);
        float4 k4 = *(const float4*)(row + 192);
        float4 v4 = *(const float4*)(row + 384);
        q4.x *= scale; q4.y *= scale; q4.z *= scale; q4.w *= scale;
        *(float4*)&qs[n][d4] = q4;
        *(float4*)&ks[n][d4] = k4;
        *(float4*)&vs[n][d4] = v4;
    }
    // zero pad rows 49..51 of q/k
    if (tid < 96) {
        int n = 49 + tid / 32, d = tid & 31;
        qs[n][d] = 0.f; ks[n][d] = 0.f;
    }
    if (tid >= 96 && tid < 148) {
        int tt = tid - 96;
        int t = tt < 49 ? tt : 48;
        int wy = w >> 6, wx = w & 63;
        int hr = wy * 7 + t / 7, wr = wx * 7 + t % 7;
        reg[tt] = ((hr >= 441) + (hr >= 445)) * 3 + (wr >= 441) + (wr >= 445);
    }
    if (tid >= 160 && tid < 185) {
        int d = tid - 160 - 12;
        int idx = d < 0 ? d + 169 : d;     // jnp negative-index wraparound
        tb[tid - 160] = table[idx * NHEADS + head];
    }
    __syncthreads();

    // score phase: 169 tiles of 4x4, one per thread, packed f32x2 dots
    if (tid < 169) {
        int n0 = (tid / 13) * 4, m0 = (tid % 13) * 4;
        unsigned long long acc2[4][4];
        #pragma unroll
        for (int i = 0; i < 4; i++)
            #pragma unroll
            for (int j = 0; j < 4; j++) acc2[i][j] = 0ULL;
        #pragma unroll
        for (int dc = 0; dc < 8; dc++) {
            ulonglong2 q2[4], k2[4];
            #pragma unroll
            for (int i = 0; i < 4; i++) q2[i] = *(const ulonglong2*)&qs[n0 + i][dc * 4];
            #pragma unroll
            for (int j = 0; j < 4; j++) k2[j] = *(const ulonglong2*)&ks[m0 + j][dc * 4];
            #pragma unroll
            for (int i = 0; i < 4; i++)
                #pragma unroll
                for (int j = 0; j < 4; j++) {
                    fma2(acc2[i][j], q2[i].x, k2[j].x);
                    fma2(acc2[i][j], q2[i].y, k2[j].y);
                }
        }
        #pragma unroll
        for (int i = 0; i < 4; i++) {
            int n = n0 + i;
            int nr = n / 7, nc = n % 7;
            #pragma unroll
            for (int j = 0; j < 4; j++) {
                int m = m0 + j;
                float v = f2lo(acc2[i][j]) + f2hi(acc2[i][j])
                        + tb[(nr - m / 7) + (nc - m % 7) + 12];
                if (reg[n] != reg[m]) v -= 100.f;
                S[n][m] = v;
            }
        }
    }
    __syncthreads();

    int lane = tid & 31, wrp = tid >> 5;
    for (int n = wrp; n < 49; n += 6) {
        float v0 = S[n][lane];
        bool has2 = (lane + 32) < 49;
        float v1 = has2 ? S[n][lane + 32] : -1e30f;
        float mx = fmaxf(v0, v1);
        #pragma unroll
        for (int o = 16; o; o >>= 1) mx = fmaxf(mx, __shfl_xor_sync(0xffffffffu, mx, o));
        float e0 = __expf(v0 - mx);
        float e1 = has2 ? __expf(v1 - mx) : 0.f;
        float sm = e0 + e1;
        #pragma unroll
        for (int o = 16; o; o >>= 1) sm += __shfl_xor_sync(0xffffffffu, sm, o);
        float inv = 1.f / sm;
        S[n][lane] = e0 * inv;
        if (has2) S[n][lane + 32] = e1 * inv;
    }
    __syncthreads();

    // PV phase: 13 n-tiles x 8 d-tiles of 4n x 4d  (104 threads), scalar S
    if (tid < 104) {
        int n0 = (tid >> 3) * 4, d0 = (tid & 7) * 4;
        unsigned long long a2[4][2];
        #pragma unroll
        for (int i = 0; i < 4; i++) { a2[i][0] = 0ULL; a2[i][1] = 0ULL; }
        for (int m = 0; m < 49; m++) {
            unsigned long long v01 = *(const unsigned long long*)&vs[m][d0];
            unsigned long long v23 = *(const unsigned long long*)&vs[m][d0 + 2];
            #pragma unroll
            for (int i = 0; i < 4; i++) {
                unsigned long long s2 = pk2(S[n0 + i][m]);
                fma2(a2[i][0], s2, v01);
                fma2(a2[i][1], s2, v23);
            }
        }
        #pragma unroll
        for (int i = 0; i < 4; i++) {
            int n = n0 + i;
            if (n < 49) {
                float o0 = f2lo(a2[i][0]), o1 = f2hi(a2[i][0]);
                float o2 = f2lo(a2[i][1]), o3 = f2hi(a2[i][1]);
                __nv_bfloat16 h0 = __float2bfloat16(o0), h1 = __float2bfloat16(o1);
                __nv_bfloat16 h2 = __float2bfloat16(o2), h3 = __float2bfloat16(o3);
                __nv_bfloat162 hh0, hh1, ll0, ll1;
                hh0.x = h0; hh0.y = h1; hh1.x = h2; hh1.y = h3;
                ll0.x = __float2bfloat16(o0 - __bfloat162float(h0));
                ll0.y = __float2bfloat16(o1 - __bfloat162float(h1));
                ll1.x = __float2bfloat16(o2 - __bfloat162float(h2));
                ll1.y = __float2bfloat16(o3 - __bfloat162float(h3));
                size_t ob = ((size_t)w * 49 + n) * 192 + head * 32 + d0;
                *(__nv_bfloat162*)(oh + ob)     = hh0;
                *(__nv_bfloat162*)(oh + ob + 2) = hh1;
                *(__nv_bfloat162*)(ol + ob)     = ll0;
                *(__nv_bfloat162*)(ol + ob + 2) = ll1;
            }
        }
    }
}

// ---------------------------------------------------------------------------
extern "C" void kernel_launch(void* const* d_in, const int* in_sizes, int n_in,
                              void* d_out, int out_size) {
    (void)in_sizes; (void)n_in; (void)out_size;
    const float* x      = (const float*)d_in[0];
    const float* qkv_w  = (const float*)d_in[1];
    const float* qkv_b  = (const float*)d_in[2];
    const float* proj_w = (const float*)d_in[3];
    const float* proj_b = (const float*)d_in[4];
    const float* table  = (const float*)d_in[5];
    float* out = (float*)d_out;

    __nv_bfloat16 *xh, *xl, *ah, *al, *wqh, *wql, *wph, *wpl;
    float *qkvb;
    cudaGetSymbolAddress((void**)&xh,  g_xh);
    cudaGetSymbolAddress((void**)&xl,  g_xl);
    cudaGetSymbolAddress((void**)&qkvb, g_qkv);
    cudaGetSymbolAddress((void**)&ah,  g_ah);
    cudaGetSymbolAddress((void**)&al,  g_al);
    cudaGetSymbolAddress((void**)&wqh, g_wqh);
    cudaGetSymbolAddress((void**)&wql, g_wql);
    cudaGetSymbolAddress((void**)&wph, g_wph);
    cudaGetSymbolAddress((void**)&wpl, g_wpl);

    cudaFuncSetAttribute(hmma_gemm<0>, cudaFuncAttributeMaxDynamicSharedMemorySize, SMEM_TOTAL);
    cudaFuncSetAttribute(hmma_gemm<1>, cudaFuncAttributeMaxDynamicSharedMemorySize, SMEM_TOTAL);

    wsplit_kernel<<<(576 * 192 + 255) / 256, 256>>>(qkv_w, wqh, wql, 576 * 192);
    wsplit_kernel<<<(192 * 192 + 255) / 256, 256>>>(proj_w, wph, wpl, 192 * 192);
    gather_kernel<<<dim3(NTOK / 32, 192 / 32), dim3(32, 32)>>>(x);

    hmma_gemm<0><<<dim3(6, NTOK / 128), 256, SMEM_TOTAL>>>(xh, xl, wqh, wql, qkv_b, qkvb, 576);
    attn_kernel<<<NWIN * NHEADS, 192>>>(qkvb, table, ah, al);
    hmma_gemm<1><<<dim3(2, NTOK / 128), 256, SMEM_TOTAL>>>(ah, al, wph, wpl, proj_b, out, 192);
}